// round 7
// baseline (speedup 1.0000x reference)
#include <cuda_runtime.h>
#include <math.h>

#define NN 512
#define SD 64
#define ED 16
#define LL 5
#define DOUT 97
#define EPG 4032
#define NCTA 128
#define TPB 256
#define MAXE (NN*63)
#define RSTR 120

#define OFF_V (NN*SD)
#define OFF_E (OFF_V + NN*48)
#define OFF_P (OFF_E + 8*EPG*ED)

// ---- shared layout (float offsets) ----
#define SH_W2T   0        /* 64*65 : W2 cols 0..63 transposed */
#define SH_W2T2  4160     /* 33*65 (+pad) : W2 cols 64..96 transposed */
#define SH_W1T   6308     /* 18*64 : W1 rows 128..145 (reused for Wpre) */
#define SH_WPS   7460     /* 256 : Wpost */
#define SH_W1S   7716     /* 8192 : W1 rows 0..127 (reused Wm1|Wm2) */
#define SH_P     15908    /* 1536 : all nodes p */
#define SH_PN    17444    /* 1536 : all nodes pn (reused: original p at output) */
#define SH_F     18980    /* 8192 : all nodes f */
#define SH_TB    27172    /* 36 : b2 tail biases */
#define SH_H     27208    /* 4*140 : per-group h buffers */
#define SH_RED   27768    /* 4*8 : reductions */
#define SH_ENV   27800    /* 4 : env sums */
#define SH_HW    27804    /* 8*64 : per-warp h buffers */
#define SH_EI    28316    /* 256*16 : E slice */
#define SH_IT    32412    /* 256 ints : item slice */
#define SH_TOTAL 32668
#define SMEM_BYTES (SH_TOTAL*4)

// ---------------- device state ----------------
__device__ float g_ci[NN*SD];
__device__ float g_cj[NN*SD];
__device__ float g_vn[NN*48];
__device__ float g_p[2][NN*3];
__device__ float g_pn[NN*3];
__device__ float g_f[NN*ED];
__device__ float g_deginv[NN];
__device__ int   g_off[NN+1];
__device__ int   g_items[MAXE];
__device__ float g_rec[(size_t)MAXE*RSTR];
__device__ unsigned int g_ctr;

__device__ __forceinline__ void grpbar(int grp) {
    asm volatile("bar.sync %0, 64;" :: "r"(grp + 1) : "memory");
}
__device__ __forceinline__ float silu(float x) {
    return x * (1.0f / (1.0f + __expf(-x)));
}
__device__ __forceinline__ void gsync(unsigned int target) {
    __syncthreads();
    __threadfence();
    if (threadIdx.x == 0) {
        atomicAdd(&g_ctr, 1u);
        volatile unsigned int* c = &g_ctr;
        while (*c < target) { }
        __threadfence();
    }
    __syncthreads();
}

// ---------------- init: adjacency + prefix + item list ----------------
__global__ void k_init(const float* __restrict__ p) {
    __shared__ int wsum[16];
    int n = threadIdx.x;
    int lane = n & 31, wid = n >> 5;
    int base = (n >> 6) << 6;
    float px = p[n*3], py = p[n*3+1], pz = p[n*3+2];
    int cnt = 0;
    for (int j = 0; j < 64; j++) {
        int jg = base + j;
        if (jg == n) continue;
        float dx = p[jg*3]-px, dy = p[jg*3+1]-py, dz = p[jg*3+2]-pz;
        if (dx*dx + dy*dy + dz*dz < 25.0f) cnt++;
    }
    int inc = cnt;
    #pragma unroll
    for (int o = 1; o < 32; o <<= 1) {
        int v = __shfl_up_sync(0xffffffffu, inc, o);
        if (lane >= o) inc += v;
    }
    if (lane == 31) wsum[wid] = inc;
    __syncthreads();
    if (wid == 0) {
        int v = (lane < 16) ? wsum[lane] : 0;
        #pragma unroll
        for (int o = 1; o < 32; o <<= 1) {
            int u = __shfl_up_sync(0xffffffffu, v, o);
            if (lane >= o) v += u;
        }
        if (lane < 16) wsum[lane] = v;
    }
    __syncthreads();
    int off = inc - cnt + (wid ? wsum[wid-1] : 0);
    g_off[n] = off;
    if (n == NN-1) g_off[NN] = off + cnt;
    g_deginv[n] = 1.0f / fmaxf((float)cnt, 1.0f);
    int o = off;
    for (int j = 0; j < 64; j++) {
        int jg = base + j;
        if (jg == n) continue;
        float dx = p[jg*3]-px, dy = p[jg*3+1]-py, dz = p[jg*3+2]-pz;
        if (dx*dx + dy*dy + dz*dz < 25.0f) g_items[o++] = (n << 6) | j;
    }
    g_p[0][n*3] = px; g_p[0][n*3+1] = py; g_p[0][n*3+2] = pz;
    if (n == 0) g_ctr = 0u;
}

__global__ void __launch_bounds__(TPB, 1)
k_fused(const float* __restrict__ s_in, const float* __restrict__ v_in,
        const float* __restrict__ p_in, const float* __restrict__ ea,
        const float* __restrict__ ln_g, const float* __restrict__ ln_b,
        const float* __restrict__ W1,  const float* __restrict__ b1,
        const float* __restrict__ W2,  const float* __restrict__ b2,
        const float* __restrict__ Wm1, const float* __restrict__ bm1,
        const float* __restrict__ Wm2, const float* __restrict__ bm2,
        const float* __restrict__ Wpre,const float* __restrict__ bpre,
        const float* __restrict__ Wpost,const float* __restrict__ bpost,
        float* __restrict__ out)
{
    extern __shared__ float sh[];
    int* s_it = (int*)(sh + SH_IT);
    const int tx   = threadIdx.x;
    const int grp  = tx >> 6;
    const int t    = tx & 63;
    const int lane = tx & 31;
    const int widx = tx >> 5;
    const int wrp  = t >> 5;
    const int i    = blockIdx.x * 4 + grp;   // owned node
    unsigned int epoch = 0;

    float* shHb = sh + SH_H + grp*140;

    // -------- init --------
    float s_reg = s_in[i*SD + t];
    float v_reg = (t < 48) ? v_in[i*48 + t] : 0.0f;
    const float dinv = g_deginv[i];

    const int T   = g_off[NN];
    const int it0 = (blockIdx.x * T) >> 7;
    const int it1 = ((blockIdx.x + 1) * T) >> 7;
    const int nsl = it1 - it0;

    for (int idx = tx; idx < nsl; idx += TPB) s_it[idx] = g_items[it0 + idx];
    __syncthreads();
    for (int idx = tx; idx < nsl*ED; idx += TPB) {
        int item = s_it[idx >> 4];
        int c = idx & 15;
        int ii = item >> 6, jl = item & 63;
        int li = ii & 63, gg = ii >> 6;
        int e = gg*EPG + li*63 + jl - (jl > li ? 1 : 0);
        sh[SH_EI + idx] = ea[(size_t)e*ED + c];
    }

    // -------- layers --------
    for (int l = 0; l < LL; l++) {
        const int pin = l & 1, pout = pin ^ 1;

        __syncthreads();
        {
            const float4* w1g = (const float4*)(W1 + (size_t)l*146*SD);
            float4* w1s = (float4*)(sh + SH_W1S);
            for (int idx = tx; idx < 128*SD/4; idx += TPB) w1s[idx] = w1g[idx];
        }
        __syncthreads();

        // ---- node_pre ----
        {
            float xs = s_reg, xq = s_reg*s_reg;
            float xv = (t < 48) ? v_reg*v_reg : 0.0f;
            #pragma unroll
            for (int o = 16; o; o >>= 1) {
                xs += __shfl_down_sync(0xffffffffu, xs, o);
                xq += __shfl_down_sync(0xffffffffu, xq, o);
                xv += __shfl_down_sync(0xffffffffu, xv, o);
            }
            grpbar(grp);
            if (lane == 0) {
                float* r = sh + SH_RED + grp*8 + wrp*3;
                r[0] = xs; r[1] = xq; r[2] = xv;
            }
            grpbar(grp);
            const float* r = sh + SH_RED + grp*8;
            float mu   = (r[0] + r[3]) * (1.0f/64);
            float var  = (r[1] + r[4]) * (1.0f/64) - mu*mu;
            float vinv = rsqrtf((r[2] + r[5]) * (1.0f/16) + 1e-6f);
            s_reg = (s_reg - mu) * rsqrtf(fmaxf(var, 0.0f) + 1e-6f) * ln_g[l*SD + t] + ln_b[l*SD + t];
            shHb[t] = s_reg;
            if (t < 48) { v_reg *= vinv; g_vn[i*48 + t] = v_reg; }
            grpbar(grp);

            const float* w1s = sh + SH_W1S;
            float c0 = b1[l*SD + t], c1 = 0.0f, d0 = 0.0f, d1 = 0.0f;
            #pragma unroll 8
            for (int k = 0; k < SD; k += 2) {
                float a = shHb[k], b = shHb[k+1];
                c0 += a * w1s[k*SD + t];
                c1 += b * w1s[(k+1)*SD + t];
                d0 += a * w1s[(64+k)*SD + t];
                d1 += b * w1s[(65+k)*SD + t];
            }
            g_ci[i*SD + t] = c0 + c1;
            g_cj[i*SD + t] = d0 + d1;

            if (t < 3) {
                float p0 = g_p[pin][i*3], p1 = g_p[pin][i*3+1], p2 = g_p[pin][i*3+2];
                float inv = rsqrtf(p0*p0 + p1*p1 + p2*p2);
                g_pn[i*3 + t] = g_p[pin][i*3 + t] * inv;
            }
        }

        gsync(++epoch * NCTA);   // A: ci/cj/vn/pn/p(l) + f(l-1) visible

        // ---- stage all-node dynamics + weights ----
        for (int idx = tx; idx < NN*3; idx += TPB) {
            sh[SH_P + idx]  = g_p[pin][idx];
            sh[SH_PN + idx] = g_pn[idx];
        }
        if (l > 0) {
            const float4* fg = (const float4*)g_f;
            float4* fs = (float4*)(sh + SH_F);
            for (int idx = tx; idx < NN*ED/4; idx += TPB) fs[idx] = fg[idx];
            for (int idx = tx; idx < ED*ED; idx += TPB)
                sh[SH_WPS + idx] = Wpost[(l-1)*ED*ED + idx];
        }
        {
            const float* w2g = W2 + (size_t)l*SD*DOUT;
            for (int idx = tx; idx < SD*DOUT; idx += TPB) {
                int kk = idx / DOUT, col = idx - kk*DOUT;
                float w = w2g[idx];
                if (col < 64) sh[SH_W2T + col*65 + kk] = w;
                else          sh[SH_W2T2 + (col-64)*65 + kk] = w;
            }
            for (int idx = tx; idx < 18*SD; idx += TPB)
                sh[SH_W1T + idx] = W1[(size_t)l*146*SD + 128*SD + idx];
            for (int idx = tx; idx < 33; idx += TPB)
                sh[SH_TB + idx] = b2[l*DOUT + 64 + idx];
        }
        __syncthreads();

        // ---- edge update (layer l-1), slice-parallel ----
        if (l > 0) {
            int hw = lane >> 4, e = lane & 15;
            float bp = bpost[(l-1)*ED + e];
            for (int b = it0 + widx*2; b < it1; b += 16) {
                int k = b + hw;
                bool act = (k < it1);
                int sl = (act ? k : it0) - it0;
                int item = s_it[sl];
                int ii = item >> 6, jl = item & 63;
                int jg = ((ii >> 6) << 6) + jl;
                float x = sh[SH_F + ii*ED + e] + sh[SH_F + jg*ED + e];
                float tv = sh[SH_EI + sl*ED + e] + silu(x);
                float o = bp;
                #pragma unroll
                for (int m = 0; m < ED; m++) {
                    float tm = __shfl_sync(0xffffffffu, tv, (hw << 4) + m);
                    o += tm * sh[SH_WPS + m*ED + e];
                }
                if (act) sh[SH_EI + sl*ED + e] = o;
            }
        }
        __syncthreads();

        // ---- pair phase: slice items, one warp per item ----
        {
            const float* w1t = sh + SH_W1T;
            float* hb = sh + SH_HW + widx*64;
            const float b2g = sh[SH_TB + 32];

            for (int k = it0 + widx; k < it1; k += 8) {
                int sl = k - it0;
                int item = s_it[sl];
                int ii = item >> 6, jl = item & 63;
                int jg = ((ii >> 6) << 6) + jl;

                float pix = sh[SH_P + ii*3], piy = sh[SH_P + ii*3+1], piz = sh[SH_P + ii*3+2];
                float dx = sh[SH_P + jg*3]-pix, dy = sh[SH_P + jg*3+1]-piy, dz = sh[SH_P + jg*3+2]-piz;
                float dd = sqrtf(fmaxf(dx*dx + dy*dy + dz*dz, 1e-6f));
                float ac = sh[SH_PN + ii*3]*sh[SH_PN + jg*3]
                         + sh[SH_PN + ii*3+1]*sh[SH_PN + jg*3+1]
                         + sh[SH_PN + ii*3+2]*sh[SH_PN + jg*3+2];
                float env = 0.5f*(__cosf(dd*0.62831853f) + 1.0f);
                float ri = 1.0f/(1.0f + dd);
                float rnx = dx*ri, rny = dy*ri, rnz = dz*ri;

                float hvA = g_ci[ii*SD + lane]      + g_cj[jg*SD + lane];
                float hvB = g_ci[ii*SD + 32 + lane] + g_cj[jg*SD + 32 + lane];
                hvA += dd*w1t[lane]      + ac*w1t[64 + lane];
                hvB += dd*w1t[32 + lane] + ac*w1t[96 + lane];
                const float4* Ep = (const float4*)(sh + SH_EI + sl*ED);
                #pragma unroll
                for (int q = 0; q < 4; q++) {
                    float4 E4 = Ep[q];
                    const float* wr = w1t + (2 + q*4)*64;
                    hvA += E4.x*wr[lane]       + E4.y*wr[64 + lane]
                         + E4.z*wr[128 + lane] + E4.w*wr[192 + lane];
                    hvB += E4.x*wr[32 + lane]  + E4.y*wr[96 + lane]
                         + E4.z*wr[160 + lane] + E4.w*wr[224 + lane];
                }
                float hpA = silu(hvA)*env;
                float hpB = silu(hvB)*env;

                float gcp = hpA*sh[SH_W2T2 + 32*65 + lane] + hpB*sh[SH_W2T2 + 32*65 + 32 + lane];
                #pragma unroll
                for (int o = 16; o; o >>= 1) gcp += __shfl_xor_sync(0xffffffffu, gcp, o);
                float gc = gcp + b2g*env;

                hb[lane] = hpA; hb[32 + lane] = hpB;
                __syncwarp();
                const float* wc = sh + SH_W2T2 + lane*65;
                const float4* h4 = (const float4*)hb;
                float a0=0,a1=0,a2=0,a3=0;
                #pragma unroll
                for (int q = 0; q < 16; q++) {
                    float4 h = h4[q];
                    a0 += h.x*wc[q*4];   a1 += h.y*wc[q*4+1];
                    a2 += h.z*wc[q*4+2]; a3 += h.w*wc[q*4+3];
                }
                float tailv = (a0+a1)+(a2+a3) + sh[SH_TB + lane]*env;
                __syncwarp();

                int d = lane & 15;
                float gr = __shfl_sync(0xffffffffu, tailv, d);
                float gv = __shfl_sync(0xffffffffu, tailv, 16 + d);
                float rnA = (lane < 16) ? rnx : rny;
                float vA = rnA*gr;
                float vB = rnz*gr;
                if (l > 0) {
                    vA += g_vn[jg*48 + lane]*gv;
                    if (lane < 16) vB += g_vn[jg*48 + 32 + lane]*gv;
                }
                float* rec = g_rec + (size_t)k*RSTR;
                rec[lane]      = hpA;
                rec[32 + lane] = hpB;
                rec[64 + lane] = vA;
                if (lane < 16) rec[96 + lane] = vB;
                if (lane < 3)  rec[112 + lane] = gc * ((lane==0)?rnx:((lane==1)?rny:rnz));
                if (lane == 0) rec[115] = env;
            }
        }

        gsync(++epoch * NCTA);   // B: records visible

        // ---- stage node_post weights ----
        if (l < LL-1) {
            const float4* m1 = (const float4*)(Wm1 + (size_t)l*SD*SD);
            const float4* m2 = (const float4*)(Wm2 + (size_t)l*SD*SD);
            float4* w1s = (float4*)(sh + SH_W1S);
            for (int idx = tx; idx < SD*SD/4; idx += TPB) {
                w1s[idx] = m1[idx];
                w1s[SD*SD/4 + idx] = m2[idx];
            }
        }
        for (int idx = tx; idx < SD*ED; idx += TPB)
            sh[SH_W1T + idx] = Wpre[(size_t)l*SD*ED + idx];
        __syncthreads();

        // ---- owner reduction + state update ----
        {
            int o0 = g_off[i], o1 = g_off[i+1];
            float h0 = 0.0f, h1 = 0.0f, b0v = 0.0f, b1v = 0.0f;
            int k = o0;
            for (; k + 1 < o1; k += 2) {
                const float* r0 = g_rec + (size_t)k*RSTR;
                const float* r1 = g_rec + (size_t)(k+1)*RSTR;
                h0 += r0[t]; h1 += r1[t];
                if (t < 52) { b0v += r0[64 + t]; b1v += r1[64 + t]; }
            }
            if (k < o1) {
                const float* r0 = g_rec + (size_t)k*RSTR;
                h0 += r0[t];
                if (t < 52) b0v += r0[64 + t];
            }
            float henv_t = h0 + h1;
            float accb   = b0v + b1v;
            shHb[t] = henv_t;
            if (t == 51) sh[SH_ENV + grp] = accb;
            grpbar(grp);
            float envs = sh[SH_ENV + grp];
            {
                const float4* hs = (const float4*)shHb;
                const float*  wc = sh + SH_W2T + t*65;
                float a0=0,a1=0,a2=0,a3=0;
                #pragma unroll
                for (int q = 0; q < 16; q++) {
                    float4 h4 = hs[q];
                    a0 += h4.x*wc[q*4];   a1 += h4.y*wc[q*4+1];
                    a2 += h4.z*wc[q*4+2]; a3 += h4.w*wc[q*4+3];
                }
                s_reg += (a0+a1)+(a2+a3) + b2[l*DOUT + t]*envs;
            }
            if (t < 48) v_reg += accb * dinv;
            if (t >= 48 && t < 51)
                g_p[pout][i*3 + (t-48)] = sh[SH_P + i*3 + (t-48)] + accb * dinv;
            grpbar(grp);
        }

        // ---- node_post ----
        {
            if (l < LL-1) {
                shHb[t] = s_reg;
                grpbar(grp);
                const float* wm1 = sh + SH_W1S;
                float h0 = bm1[l*SD + t], h1 = 0.0f;
                #pragma unroll 8
                for (int k = 0; k < SD; k += 2) {
                    h0 += shHb[k]   * wm1[k*SD + t];
                    h1 += shHb[k+1] * wm1[(k+1)*SD + t];
                }
                float hm = silu(h0 + h1);
                shHb[68 + t] = hm;
                grpbar(grp);
                const float* wm2 = sh + SH_W1S + SD*SD;
                float o0 = bm2[l*SD + t], o1 = 0.0f;
                #pragma unroll 8
                for (int k = 0; k < SD; k += 2) {
                    o0 += shHb[68+k]   * wm2[k*SD + t];
                    o1 += shHb[68+k+1] * wm2[(k+1)*SD + t];
                }
                s_reg += o0 + o1;
                grpbar(grp);
            }
            shHb[t] = s_reg;
            grpbar(grp);
            if (t < ED) {
                const float* wp = sh + SH_W1T;
                float f0 = bpre[l*ED + t], f1 = 0.0f;
                #pragma unroll 8
                for (int k = 0; k < SD; k += 2) {
                    f0 += shHb[k]   * wp[k*ED + t];
                    f1 += shHb[k+1] * wp[(k+1)*ED + t];
                }
                g_f[i*ED + t] = f0 + f1;
            }
        }
    }

    gsync(++epoch * NCTA);   // publish f(LL-1)

    // ---- final edge update ----
    {
        const float4* fg = (const float4*)g_f;
        float4* fs = (float4*)(sh + SH_F);
        for (int idx = tx; idx < NN*ED/4; idx += TPB) fs[idx] = fg[idx];
        for (int idx = tx; idx < ED*ED; idx += TPB)
            sh[SH_WPS + idx] = Wpost[(LL-1)*ED*ED + idx];
        // stage ORIGINAL p for the adjacency predicate in the output pass
        for (int idx = tx; idx < NN*3; idx += TPB) sh[SH_PN + idx] = p_in[idx];
    }
    __syncthreads();
    {
        int hw = lane >> 4, e = lane & 15;
        float bp = bpost[(LL-1)*ED + e];
        for (int b = it0 + widx*2; b < it1; b += 16) {
            int k = b + hw;
            bool act = (k < it1);
            int sl = (act ? k : it0) - it0;
            int item = s_it[sl];
            int ii = item >> 6, jl = item & 63;
            int jg = ((ii >> 6) << 6) + jl;
            float x = sh[SH_F + ii*ED + e] + sh[SH_F + jg*ED + e];
            float tv = sh[SH_EI + sl*ED + e] + silu(x);
            float o = bp;
            #pragma unroll
            for (int m = 0; m < ED; m++) {
                float tm = __shfl_sync(0xffffffffu, tv, (hw << 4) + m);
                o += tm * sh[SH_WPS + m*ED + e];
            }
            if (act) sh[SH_EI + sl*ED + e] = o;
        }
    }
    __syncthreads();

    // -------- output --------
    out[i*SD + t] = s_reg;
    if (t < 48) out[OFF_V + i*48 + t] = v_reg;
    if (t < 3)  out[OFF_P + i*3 + t] = g_p[LL & 1][i*3 + t];

    // masked (adjacent) edges: written by slice owner from updated E
    for (int idx = tx; idx < nsl*ED; idx += TPB) {
        int item = s_it[idx >> 4];
        int c = idx & 15;
        int ii = item >> 6, jl = item & 63;
        int li = ii & 63, gg = ii >> 6;
        int e = gg*EPG + li*63 + jl - (jl > li ? 1 : 0);
        out[OFF_E + (size_t)e*ED + c] = sh[SH_EI + idx];
    }

    // non-adjacent edges: pass through original edge_attr (disjoint from above)
    {
        const int e0 = blockIdx.x * (8*EPG / NCTA);        // 252 edges per CTA
        for (int q = tx; q < (8*EPG/NCTA)*ED; q += TPB) {
            int e = e0 + (q >> 4), c = q & 15;
            int gg2 = e / EPG, rem = e - gg2*EPG;
            int si = rem / 63, t63 = rem - si*63;
            int ti = t63 + (t63 >= si ? 1 : 0);
            int a = gg2*64 + si, b = gg2*64 + ti;
            float dx = sh[SH_PN + a*3]   - sh[SH_PN + b*3];
            float dy = sh[SH_PN + a*3+1] - sh[SH_PN + b*3+1];
            float dz = sh[SH_PN + a*3+2] - sh[SH_PN + b*3+2];
            if (!(dx*dx + dy*dy + dz*dz < 25.0f))
                out[OFF_E + (size_t)e*ED + c] = ea[(size_t)e*ED + c];
        }
    }
}

// ---------------- launch ----------------
extern "C" void kernel_launch(void* const* d_in, const int* in_sizes, int n_in,
                              void* d_out, int out_size) {
    const float* s    = (const float*)d_in[0];
    const float* v    = (const float*)d_in[1];
    const float* p    = (const float*)d_in[2];
    const float* ea   = (const float*)d_in[3];
    const float* ln_g = (const float*)d_in[6];
    const float* ln_b = (const float*)d_in[7];
    const float* W1   = (const float*)d_in[8];
    const float* b1   = (const float*)d_in[9];
    const float* W2   = (const float*)d_in[10];
    const float* b2   = (const float*)d_in[11];
    const float* Wm1  = (const float*)d_in[12];
    const float* bm1  = (const float*)d_in[13];
    const float* Wm2  = (const float*)d_in[14];
    const float* bm2  = (const float*)d_in[15];
    const float* Wpre = (const float*)d_in[16];
    const float* bpre = (const float*)d_in[17];
    const float* Wpost= (const float*)d_in[18];
    const float* bpost= (const float*)d_in[19];
    float* out = (float*)d_out;

    cudaFuncSetAttribute(k_fused, cudaFuncAttributeMaxDynamicSharedMemorySize, SMEM_BYTES);
    k_init<<<1, NN>>>(p);
    k_fused<<<NCTA, TPB, SMEM_BYTES>>>(s, v, p, ea, ln_g, ln_b, W1, b1, W2, b2,
                                       Wm1, bm1, Wm2, bm2, Wpre, bpre, Wpost, bpost, out);
}

// round 8
// speedup vs baseline: 1.2797x; 1.2797x over previous
#include <cuda_runtime.h>
#include <math.h>

#define NN 512
#define SD 64
#define ED 16
#define LL 5
#define DOUT 97
#define EPG 4032
#define NCTA 128
#define TPB 512
#define RS 116
#define RECCAP 160

#define OFF_V (NN*SD)
#define OFF_E (OFF_V + NN*48)
#define OFF_P (OFF_E + 8*EPG*ED)

// ---- shared layout (float offsets) ----
#define SH_W2T   0        /* 64*65 */
#define SH_W2T2  4160     /* 33*65 + pad */
#define SH_W1T   6308     /* 18*64 (reused for Wpre) */
#define SH_WPS   7460     /* 256 */
#define SH_W1S   7716     /* 8192 : W1 rows 0..127 (reused Wm1|Wm2) */
#define SH_CJ    15908    /* 4096 : group cj */
#define SH_CI    20004    /* 256 : own nodes ci */
#define SH_V     20260    /* 3072 : group vn */
#define SH_P     23332    /* 192 */
#define SH_PN    23524    /* 192 */
#define SH_F     23716    /* 1024 */
#define SH_TB    24740    /* 40 */
#define SH_H     24780    /* 4*140 */
#define SH_RED   25340    /* 32 */
#define SH_ENV   25372    /* 4 */
#define SH_HW    25376    /* 16*64 */
#define SH_EI    26400    /* 256*16 */
#define SH_REC   30496    /* 160*116 = 18560 */
#define SH_IT    49056    /* 256 ints */
#define SH_NBR   49312    /* 256 ints */
#define SH_OFF   49568    /* 8 ints */
#define SH_CNT   49576    /* 4 ints */
#define SH_LI    49580    /* 4 ints */
#define SH_WCNT  49584    /* 8 ints */
#define SH_TOTAL 49592
#define SMEM_BYTES (SH_TOTAL*4)

// ---------------- device state ----------------
__device__ float g_cj[NN*SD];
__device__ float g_vn[NN*48];
__device__ float g_p[2][NN*3];
__device__ float g_pn[NN*3];
__device__ float g_f[NN*ED];
__device__ int   g_map[NN];
__device__ unsigned int g_ctr;

__device__ __forceinline__ void bar64(int grp) {
    asm volatile("bar.sync %0, 64;" :: "r"(grp + 1) : "memory");
}
__device__ __forceinline__ void bar128(int grp) {
    asm volatile("bar.sync %0, 128;" :: "r"(grp + 5) : "memory");
}
__device__ __forceinline__ float silu(float x) {
    return x * (1.0f / (1.0f + __expf(-x)));
}
__device__ __forceinline__ void gsync(unsigned int target) {
    __syncthreads();
    __threadfence();
    if (threadIdx.x == 0) {
        atomicAdd(&g_ctr, 1u);
        volatile unsigned int* c = &g_ctr;
        while (*c < target) { }
        __threadfence();
    }
    __syncthreads();
}

// ---------------- init: degree-balanced node->CTA map ----------------
__global__ void k_init(const float* __restrict__ p) {
    __shared__ int cnt_s[NN];
    int n = threadIdx.x;
    int gb = (n >> 6) << 6;
    float px = p[n*3], py = p[n*3+1], pz = p[n*3+2];
    int cnt = 0;
    for (int j = 0; j < 64; j++) {
        int jg = gb + j;
        if (jg == n) continue;
        float dx = p[jg*3]-px, dy = p[jg*3+1]-py, dz = p[jg*3+2]-pz;
        if (dx*dx + dy*dy + dz*dz < 25.0f) cnt++;
    }
    cnt_s[n] = cnt;
    __syncthreads();
    int rank = 0;
    for (int j = 0; j < 64; j++) {
        int cj = cnt_s[gb + j];
        if (cj > cnt || (cj == cnt && (gb + j) < n)) rank++;
    }
    int round = rank >> 4, pos = rank & 15;
    int cta = (round & 1) ? (15 - pos) : pos;
    g_map[(((n >> 6)*16 + cta) << 2) + round] = n;
    g_p[0][n*3] = px; g_p[0][n*3+1] = py; g_p[0][n*3+2] = pz;
    if (n == 0) g_ctr = 0u;
}

__global__ void __launch_bounds__(TPB, 1)
k_fused(const float* __restrict__ s_in, const float* __restrict__ v_in,
        const float* __restrict__ p_in, const float* __restrict__ ea,
        const float* __restrict__ ln_g, const float* __restrict__ ln_b,
        const float* __restrict__ W1,  const float* __restrict__ b1,
        const float* __restrict__ W2,  const float* __restrict__ b2,
        const float* __restrict__ Wm1, const float* __restrict__ bm1,
        const float* __restrict__ Wm2, const float* __restrict__ bm2,
        const float* __restrict__ Wpre,const float* __restrict__ bpre,
        const float* __restrict__ Wpost,const float* __restrict__ bpost,
        float* __restrict__ out)
{
    extern __shared__ float sh[];
    int* shi = (int*)sh;
    const int tx   = threadIdx.x;
    const int grp  = tx >> 7;          // node group within CTA, 0..3
    const int t128 = tx & 127;
    const int t    = tx & 63;
    const int lane = tx & 31;
    const int widx = tx >> 5;          // warp 0..15
    const bool lower = (t128 < 64);
    const int wrp  = t >> 5;           // 0/1 within lower-64
    const int gg   = blockIdx.x >> 4;  // molecular group
    const int cbase = gg << 6;
    const int i    = g_map[blockIdx.x*4 + grp];
    const int li   = i & 63;
    unsigned int epoch = 0;
    float* shHb = sh + SH_H + grp*140;

    float s_reg = s_in[i*SD + t];
    float v_reg = (t < 48) ? v_in[i*48 + t] : 0.0f;

    // -------- adjacency (lower 64 per node) --------
    if (lower) {
        float pix = p_in[i*3], piy = p_in[i*3+1], piz = p_in[i*3+2];
        int jg = cbase + t;
        float dx = p_in[jg*3]-pix, dy = p_in[jg*3+1]-piy, dz = p_in[jg*3+2]-piz;
        bool ok = (jg != i) && (dx*dx + dy*dy + dz*dz < 25.0f);
        unsigned m = __ballot_sync(0xffffffffu, ok);
        if (lane == 0) shi[SH_WCNT + grp*2 + wrp] = __popc(m);
        bar64(grp);
        int base = (wrp == 1) ? shi[SH_WCNT + grp*2] : 0;
        if (ok) shi[SH_NBR + grp*64 + base + __popc(m & ((1u << lane) - 1u))] = t;
        if (t == 0) {
            shi[SH_CNT + grp] = shi[SH_WCNT + grp*2] + shi[SH_WCNT + grp*2 + 1];
            shi[SH_LI + grp] = li;
        }
        bar64(grp);
    }
    __syncthreads();
    if (tx == 0) {
        int o = 0; shi[SH_OFF] = 0;
        #pragma unroll
        for (int n = 0; n < 4; n++) { o += shi[SH_CNT + n]; shi[SH_OFF + n + 1] = o; }
    }
    __syncthreads();
    const int cnt = shi[SH_CNT + grp];
    const float dinv = 1.0f / fmaxf((float)cnt, 1.0f);
    if (lower && t < cnt)
        shi[SH_IT + shi[SH_OFF + grp] + t] = (grp << 6) | shi[SH_NBR + grp*64 + t];
    __syncthreads();
    const int nit = shi[SH_OFF + 4];

    // E slice into smem
    for (int idx = tx; idx < nit*ED; idx += TPB) {
        int item = shi[SH_IT + (idx >> 4)];
        int c = idx & 15;
        int ig2 = item >> 6, j = item & 63;
        int lio = shi[SH_LI + ig2];
        int e = gg*EPG + lio*63 + j - (j > lio ? 1 : 0);
        sh[SH_EI + idx] = ea[(size_t)e*ED + c];
    }

    // -------- layers --------
    for (int l = 0; l < LL; l++) {
        const int pin = l & 1, pout = pin ^ 1;

        __syncthreads();
        {
            const float4* w1g = (const float4*)(W1 + (size_t)l*146*SD);
            float4* w1s = (float4*)(sh + SH_W1S);
            for (int idx = tx; idx < 128*SD/4; idx += TPB) w1s[idx] = w1g[idx];
        }
        __syncthreads();

        // ---- node_pre: LN + vnorm (lower 64), ci/cj dot (all 128) ----
        if (lower) {
            float xs = s_reg, xq = s_reg*s_reg;
            float xv = (t < 48) ? v_reg*v_reg : 0.0f;
            #pragma unroll
            for (int o = 16; o; o >>= 1) {
                xs += __shfl_down_sync(0xffffffffu, xs, o);
                xq += __shfl_down_sync(0xffffffffu, xq, o);
                xv += __shfl_down_sync(0xffffffffu, xv, o);
            }
            bar64(grp);
            if (lane == 0) {
                float* r = sh + SH_RED + grp*8 + wrp*3;
                r[0] = xs; r[1] = xq; r[2] = xv;
            }
            bar64(grp);
            const float* r = sh + SH_RED + grp*8;
            float mu   = (r[0] + r[3]) * (1.0f/64);
            float var  = (r[1] + r[4]) * (1.0f/64) - mu*mu;
            float vinv = rsqrtf((r[2] + r[5]) * (1.0f/16) + 1e-6f);
            s_reg = (s_reg - mu) * rsqrtf(fmaxf(var, 0.0f) + 1e-6f) * ln_g[l*SD + t] + ln_b[l*SD + t];
            shHb[t] = s_reg;
            if (t < 48) { v_reg *= vinv; g_vn[i*48 + t] = v_reg; }
            if (t < 3) {
                float p0 = g_p[pin][i*3], p1 = g_p[pin][i*3+1], p2 = g_p[pin][i*3+2];
                float inv = rsqrtf(p0*p0 + p1*p1 + p2*p2);
                g_pn[i*3 + t] = g_p[pin][i*3 + t] * inv;
            }
        }
        bar128(grp);
        {
            int which = t128 >> 6;
            const float* w1s = sh + SH_W1S + which*4096;
            float a0 = which ? 0.0f : b1[l*SD + t];
            float a1 = 0.0f;
            #pragma unroll 8
            for (int k = 0; k < SD; k += 2) {
                a0 += shHb[k]   * w1s[k*64 + t];
                a1 += shHb[k+1] * w1s[(k+1)*64 + t];
            }
            float acc = a0 + a1;
            if (which == 0) sh[SH_CI + grp*64 + t] = acc;
            else            g_cj[i*SD + t] = acc;
        }

        gsync(++epoch * NCTA);   // publishes cj/vn/pn/p(l) + f(l-1)

        // ---- stage group dynamics + weights ----
        {
            const float4* cjg = (const float4*)(g_cj + cbase*SD);
            float4* cjs = (float4*)(sh + SH_CJ);
            for (int idx = tx; idx < 64*SD/4; idx += TPB) cjs[idx] = cjg[idx];
            if (l > 0) {
                const float4* vg = (const float4*)(g_vn + cbase*48);
                float4* vs = (float4*)(sh + SH_V);
                for (int idx = tx; idx < 64*48/4; idx += TPB) vs[idx] = vg[idx];
                const float4* fg = (const float4*)(g_f + cbase*ED);
                float4* fs = (float4*)(sh + SH_F);
                for (int idx = tx; idx < 64*ED/4; idx += TPB) fs[idx] = fg[idx];
                for (int idx = tx; idx < ED*ED; idx += TPB)
                    sh[SH_WPS + idx] = Wpost[(l-1)*ED*ED + idx];
            }
            for (int idx = tx; idx < 192; idx += TPB) {
                sh[SH_P + idx]  = g_p[pin][cbase*3 + idx];
                sh[SH_PN + idx] = g_pn[cbase*3 + idx];
            }
            const float* w2g = W2 + (size_t)l*SD*DOUT;
            for (int idx = tx; idx < SD*DOUT; idx += TPB) {
                int kk = idx / DOUT, col = idx - kk*DOUT;
                float w = w2g[idx];
                if (col < 64) sh[SH_W2T + col*65 + kk] = w;
                else          sh[SH_W2T2 + (col-64)*65 + kk] = w;
            }
            for (int idx = tx; idx < 18*SD; idx += TPB)
                sh[SH_W1T + idx] = W1[(size_t)l*146*SD + 128*SD + idx];
            for (int idx = tx; idx < 33; idx += TPB)
                sh[SH_TB + idx] = b2[l*DOUT + 64 + idx];
            if (l < LL-1) {
                const float4* m1 = (const float4*)(Wm1 + (size_t)l*SD*SD);
                const float4* m2 = (const float4*)(Wm2 + (size_t)l*SD*SD);
                float4* w1s = (float4*)(sh + SH_W1S);
                for (int idx = tx; idx < SD*SD/4; idx += TPB) {
                    w1s[idx] = m1[idx];
                    w1s[SD*SD/4 + idx] = m2[idx];
                }
            }
        }
        __syncthreads();

        // ---- edge update (layer l-1): 16 warps, 32 half-warp processors ----
        if (l > 0) {
            int hw = lane >> 4, e = lane & 15;
            float bp = bpost[(l-1)*ED + e];
            for (int b = widx*2; b < nit; b += 32) {
                int k = b + hw;
                bool act = (k < nit);
                int sl = act ? k : 0;
                int item = shi[SH_IT + sl];
                int ig2 = item >> 6, j = item & 63;
                float x = sh[SH_F + shi[SH_LI + ig2]*ED + e] + sh[SH_F + j*ED + e];
                float tv = sh[SH_EI + sl*ED + e] + silu(x);
                float o = bp;
                #pragma unroll
                for (int m = 0; m < ED; m++) {
                    float tm = __shfl_sync(0xffffffffu, tv, (hw << 4) + m);
                    o += tm * sh[SH_WPS + m*ED + e];
                }
                if (act) sh[SH_EI + sl*ED + e] = o;
            }
        }
        __syncthreads();

        // ---- pair phase: flat items across 16 warps, records in smem ----
        {
            const float* w1t = sh + SH_W1T;
            float* hb = sh + SH_HW + widx*64;
            const float b2g = sh[SH_TB + 32];

            for (int k = widx; k < nit; k += 16) {
                int item = shi[SH_IT + k];
                int ig2 = item >> 6, j = item & 63;
                int lio = shi[SH_LI + ig2];

                float pix = sh[SH_P + lio*3], piy = sh[SH_P + lio*3+1], piz = sh[SH_P + lio*3+2];
                float dx = sh[SH_P + j*3]-pix, dy = sh[SH_P + j*3+1]-piy, dz = sh[SH_P + j*3+2]-piz;
                float dd = sqrtf(fmaxf(dx*dx + dy*dy + dz*dz, 1e-6f));
                float ac = sh[SH_PN + lio*3]*sh[SH_PN + j*3]
                         + sh[SH_PN + lio*3+1]*sh[SH_PN + j*3+1]
                         + sh[SH_PN + lio*3+2]*sh[SH_PN + j*3+2];
                float env = 0.5f*(__cosf(dd*0.62831853f) + 1.0f);
                float ri = 1.0f/(1.0f + dd);
                float rnx = dx*ri, rny = dy*ri, rnz = dz*ri;

                float hvA = sh[SH_CI + ig2*64 + lane]      + sh[SH_CJ + j*SD + lane];
                float hvB = sh[SH_CI + ig2*64 + 32 + lane] + sh[SH_CJ + j*SD + 32 + lane];
                hvA += dd*w1t[lane]      + ac*w1t[64 + lane];
                hvB += dd*w1t[32 + lane] + ac*w1t[96 + lane];
                const float4* Ep = (const float4*)(sh + SH_EI + k*ED);
                #pragma unroll
                for (int q = 0; q < 4; q++) {
                    float4 E4 = Ep[q];
                    const float* wr = w1t + (2 + q*4)*64;
                    hvA += E4.x*wr[lane]       + E4.y*wr[64 + lane]
                         + E4.z*wr[128 + lane] + E4.w*wr[192 + lane];
                    hvB += E4.x*wr[32 + lane]  + E4.y*wr[96 + lane]
                         + E4.z*wr[160 + lane] + E4.w*wr[224 + lane];
                }
                float hpA = silu(hvA)*env;
                float hpB = silu(hvB)*env;

                float gcp = hpA*sh[SH_W2T2 + 32*65 + lane] + hpB*sh[SH_W2T2 + 32*65 + 32 + lane];
                #pragma unroll
                for (int o = 16; o; o >>= 1) gcp += __shfl_xor_sync(0xffffffffu, gcp, o);
                float gc = gcp + b2g*env;

                hb[lane] = hpA; hb[32 + lane] = hpB;
                __syncwarp();
                const float* wc = sh + SH_W2T2 + lane*65;
                const float4* h4 = (const float4*)hb;
                float a0=0,a1=0,a2=0,a3=0;
                #pragma unroll
                for (int q = 0; q < 16; q++) {
                    float4 h = h4[q];
                    a0 += h.x*wc[q*4];   a1 += h.y*wc[q*4+1];
                    a2 += h.z*wc[q*4+2]; a3 += h.w*wc[q*4+3];
                }
                float tailv = (a0+a1)+(a2+a3) + sh[SH_TB + lane]*env;
                __syncwarp();

                int d = lane & 15;
                float gr = __shfl_sync(0xffffffffu, tailv, d);
                float gv = __shfl_sync(0xffffffffu, tailv, 16 + d);
                float rnA = (lane < 16) ? rnx : rny;
                float vA = rnA*gr;
                float vB = rnz*gr;
                if (l > 0) {
                    vA += sh[SH_V + j*48 + lane]*gv;
                    if (lane < 16) vB += sh[SH_V + j*48 + 32 + lane]*gv;
                }
                float* rec = sh + SH_REC + k*RS;
                rec[lane]      = hpA;
                rec[32 + lane] = hpB;
                rec[64 + lane] = vA;
                if (lane < 16) rec[96 + lane] = vB;
                if (lane < 3)  rec[112 + lane] = gc * ((lane==0)?rnx:((lane==1)?rny:rnz));
                if (lane == 0) rec[115] = env;
            }
        }
        __syncthreads();
        for (int idx = tx; idx < SD*ED; idx += TPB)
            sh[SH_W1T + idx] = Wpre[(size_t)l*SD*ED + idx];
        __syncthreads();

        // ---- owner reduction + state update + node_post (lower 64) ----
        if (lower) {
            int o0 = shi[SH_OFF + grp], o1 = shi[SH_OFF + grp + 1];
            float h0 = 0.0f, h1 = 0.0f, b0v = 0.0f, b1v = 0.0f;
            int k = o0;
            for (; k + 1 < o1; k += 2) {
                h0 += sh[SH_REC + k*RS + t];
                h1 += sh[SH_REC + (k+1)*RS + t];
                if (t < 52) {
                    b0v += sh[SH_REC + k*RS + 64 + t];
                    b1v += sh[SH_REC + (k+1)*RS + 64 + t];
                }
            }
            if (k < o1) {
                h0 += sh[SH_REC + k*RS + t];
                if (t < 52) b0v += sh[SH_REC + k*RS + 64 + t];
            }
            float henv = h0 + h1, accb = b0v + b1v;
            shHb[t] = henv;
            if (t == 51) sh[SH_ENV + grp] = accb;
            bar64(grp);
            float envs = sh[SH_ENV + grp];
            {
                const float4* hs = (const float4*)shHb;
                const float*  wc = sh + SH_W2T + t*65;
                float a0=0,a1=0,a2=0,a3=0;
                #pragma unroll
                for (int q = 0; q < 16; q++) {
                    float4 h4 = hs[q];
                    a0 += h4.x*wc[q*4];   a1 += h4.y*wc[q*4+1];
                    a2 += h4.z*wc[q*4+2]; a3 += h4.w*wc[q*4+3];
                }
                s_reg += (a0+a1)+(a2+a3) + b2[l*DOUT + t]*envs;
            }
            if (t < 48) v_reg += accb * dinv;
            if (t >= 48 && t < 51)
                g_p[pout][i*3 + (t-48)] = sh[SH_P + li*3 + (t-48)] + accb * dinv;
            bar64(grp);

            if (l < LL-1) {
                shHb[t] = s_reg;
                bar64(grp);
                const float* wm1 = sh + SH_W1S;
                float m0 = bm1[l*SD + t], m1 = 0.0f;
                #pragma unroll 8
                for (int kk = 0; kk < SD; kk += 2) {
                    m0 += shHb[kk]   * wm1[kk*SD + t];
                    m1 += shHb[kk+1] * wm1[(kk+1)*SD + t];
                }
                float hm = silu(m0 + m1);
                shHb[68 + t] = hm;
                bar64(grp);
                const float* wm2 = sh + SH_W1S + SD*SD;
                float q0 = bm2[l*SD + t], q1 = 0.0f;
                #pragma unroll 8
                for (int kk = 0; kk < SD; kk += 2) {
                    q0 += shHb[68+kk]   * wm2[kk*SD + t];
                    q1 += shHb[68+kk+1] * wm2[(kk+1)*SD + t];
                }
                s_reg += q0 + q1;
                bar64(grp);
            }
            shHb[t] = s_reg;
            bar64(grp);
            if (t < ED) {
                const float* wp = sh + SH_W1T;
                float f0 = bpre[l*ED + t], f1 = 0.0f;
                #pragma unroll 8
                for (int kk = 0; kk < SD; kk += 2) {
                    f0 += shHb[kk]   * wp[kk*ED + t];
                    f1 += shHb[kk+1] * wp[(kk+1)*ED + t];
                }
                g_f[i*ED + t] = f0 + f1;
            }
        }
    }

    gsync(++epoch * NCTA);   // publish f(LL-1)

    // ---- final edge update ----
    {
        const float4* fg = (const float4*)(g_f + cbase*ED);
        float4* fs = (float4*)(sh + SH_F);
        for (int idx = tx; idx < 64*ED/4; idx += TPB) fs[idx] = fg[idx];
        for (int idx = tx; idx < ED*ED; idx += TPB)
            sh[SH_WPS + idx] = Wpost[(LL-1)*ED*ED + idx];
    }
    __syncthreads();
    {
        int hw = lane >> 4, e = lane & 15;
        float bp = bpost[(LL-1)*ED + e];
        for (int b = widx*2; b < nit; b += 32) {
            int k = b + hw;
            bool act = (k < nit);
            int sl = act ? k : 0;
            int item = shi[SH_IT + sl];
            int ig2 = item >> 6, j = item & 63;
            float x = sh[SH_F + shi[SH_LI + ig2]*ED + e] + sh[SH_F + j*ED + e];
            float tv = sh[SH_EI + sl*ED + e] + silu(x);
            float o = bp;
            #pragma unroll
            for (int m = 0; m < ED; m++) {
                float tm = __shfl_sync(0xffffffffu, tv, (hw << 4) + m);
                o += tm * sh[SH_WPS + m*ED + e];
            }
            if (act) sh[SH_EI + sl*ED + e] = o;
        }
    }
    __syncthreads();

    // -------- output --------
    if (lower) {
        out[i*SD + t] = s_reg;
        if (t < 48) out[OFF_V + i*48 + t] = v_reg;
        if (t < 3)  out[OFF_P + i*3 + t] = g_p[LL & 1][i*3 + t];
    }
    // adjacent edges from updated E
    for (int idx = tx; idx < nit*ED; idx += TPB) {
        int item = shi[SH_IT + (idx >> 4)];
        int c = idx & 15;
        int ig2 = item >> 6, j = item & 63;
        int lio = shi[SH_LI + ig2];
        int e = gg*EPG + lio*63 + j - (j > lio ? 1 : 0);
        out[OFF_E + (size_t)e*ED + c] = sh[SH_EI + idx];
    }
    // non-adjacent edges: original edge_attr passthrough (disjoint set)
    {
        const int e0 = blockIdx.x * (8*EPG / NCTA);
        for (int q = tx; q < (8*EPG/NCTA)*ED; q += TPB) {
            int e = e0 + (q >> 4), c = q & 15;
            int gg2 = e / EPG, rem = e - gg2*EPG;
            int si = rem / 63, t63 = rem - si*63;
            int ti = t63 + (t63 >= si ? 1 : 0);
            int a = gg2*64 + si, b = gg2*64 + ti;
            float dx = p_in[a*3]   - p_in[b*3];
            float dy = p_in[a*3+1] - p_in[b*3+1];
            float dz = p_in[a*3+2] - p_in[b*3+2];
            if (!(dx*dx + dy*dy + dz*dz < 25.0f))
                out[OFF_E + (size_t)e*ED + c] = ea[(size_t)e*ED + c];
        }
    }
}

// ---------------- launch ----------------
extern "C" void kernel_launch(void* const* d_in, const int* in_sizes, int n_in,
                              void* d_out, int out_size) {
    const float* s    = (const float*)d_in[0];
    const float* v    = (const float*)d_in[1];
    const float* p    = (const float*)d_in[2];
    const float* ea   = (const float*)d_in[3];
    const float* ln_g = (const float*)d_in[6];
    const float* ln_b = (const float*)d_in[7];
    const float* W1   = (const float*)d_in[8];
    const float* b1   = (const float*)d_in[9];
    const float* W2   = (const float*)d_in[10];
    const float* b2   = (const float*)d_in[11];
    const float* Wm1  = (const float*)d_in[12];
    const float* bm1  = (const float*)d_in[13];
    const float* Wm2  = (const float*)d_in[14];
    const float* bm2  = (const float*)d_in[15];
    const float* Wpre = (const float*)d_in[16];
    const float* bpre = (const float*)d_in[17];
    const float* Wpost= (const float*)d_in[18];
    const float* bpost= (const float*)d_in[19];
    float* out = (float*)d_out;

    cudaFuncSetAttribute(k_fused, cudaFuncAttributeMaxDynamicSharedMemorySize, SMEM_BYTES);
    k_init<<<1, NN>>>(p);
    k_fused<<<NCTA, TPB, SMEM_BYTES>>>(s, v, p, ea, ln_g, ln_b, W1, b1, W2, b2,
                                       Wm1, bm1, Wm2, bm2, Wpre, bpre, Wpost, bpost, out);
}

// round 9
// speedup vs baseline: 1.4406x; 1.1257x over previous
#include <cuda_runtime.h>
#include <math.h>

#define NN 512
#define SD 64
#define ED 16
#define LL 5
#define DOUT 97
#define EPG 4032
#define NCTA 128
#define TPB 512
#define RS 116

#define OFF_V (NN*SD)
#define OFF_E (OFF_V + NN*48)
#define OFF_P (OFF_E + 8*EPG*ED)

// ---- shared layout (float offsets) ----
#define SH_W2T   0        /* 64*68 : W2 cols 0..63 transposed, pad 68 */
#define SH_W2T2  4352     /* 33*68 : W2 cols 64..96 transposed, pad 68 */
#define SH_W1TT  6596     /* 64*20 : W1 rows 128..145 per-col transposed (reused Wpre) */
#define SH_WPS   7876     /* 256 */
#define SH_W1S   8132     /* 8192 : W1 rows 0..127 (reused Wm1|Wm2) */
#define SH_CJ    16324    /* 4096 */
#define SH_CI    20420    /* 256 */
#define SH_V     20676    /* 3072 */
#define SH_P     23748    /* 192 */
#define SH_PN    23940    /* 192 */
#define SH_F     24132    /* 1024 */
#define SH_TB    25156    /* 40 */
#define SH_H     25196    /* 4*140 */
#define SH_RED   25756    /* 32 */
#define SH_ENV   25788    /* 4 */
#define SH_HW    25792    /* 16*64 */
#define SH_EI    26816    /* 4096 */
#define SH_REC   30912    /* 160*116 = 18560 */
#define SH_IT    49472    /* 256 ints */
#define SH_NBR   49728    /* 256 ints */
#define SH_OFF   49984    /* 8 ints */
#define SH_CNT   49992    /* 4 ints */
#define SH_LI    49996    /* 4 ints */
#define SH_WCNT  50000    /* 8 ints */
#define SH_TOTAL 50008
#define SMEM_BYTES (SH_TOTAL*4)

// ---------------- device state ----------------
__device__ float g_cj[NN*SD];
__device__ float g_vn[NN*48];
__device__ float g_p[2][NN*3];
__device__ float g_pn[NN*3];
__device__ float g_f[NN*ED];
__device__ int   g_map[NN];
__device__ unsigned int g_ctr;

__device__ __forceinline__ void bar64(int grp) {
    asm volatile("bar.sync %0, 64;" :: "r"(grp + 1) : "memory");
}
__device__ __forceinline__ void bar128(int grp) {
    asm volatile("bar.sync %0, 128;" :: "r"(grp + 5) : "memory");
}
__device__ __forceinline__ float silu(float x) {
    return x * (1.0f / (1.0f + __expf(-x)));
}
__device__ __forceinline__ void gsync(unsigned int target) {
    __syncthreads();
    __threadfence();
    if (threadIdx.x == 0) {
        atomicAdd(&g_ctr, 1u);
        volatile unsigned int* c = &g_ctr;
        while (*c < target) { }
        __threadfence();
    }
    __syncthreads();
}

// ---------------- init: degree-balanced node->CTA map ----------------
__global__ void k_init(const float* __restrict__ p) {
    __shared__ int cnt_s[NN];
    int n = threadIdx.x;
    int gb = (n >> 6) << 6;
    float px = p[n*3], py = p[n*3+1], pz = p[n*3+2];
    int cnt = 0;
    for (int j = 0; j < 64; j++) {
        int jg = gb + j;
        if (jg == n) continue;
        float dx = p[jg*3]-px, dy = p[jg*3+1]-py, dz = p[jg*3+2]-pz;
        if (dx*dx + dy*dy + dz*dz < 25.0f) cnt++;
    }
    cnt_s[n] = cnt;
    __syncthreads();
    int rank = 0;
    for (int j = 0; j < 64; j++) {
        int cj = cnt_s[gb + j];
        if (cj > cnt || (cj == cnt && (gb + j) < n)) rank++;
    }
    int round = rank >> 4, pos = rank & 15;
    int cta = (round & 1) ? (15 - pos) : pos;
    g_map[(((n >> 6)*16 + cta) << 2) + round] = n;
    g_p[0][n*3] = px; g_p[0][n*3+1] = py; g_p[0][n*3+2] = pz;
    if (n == 0) g_ctr = 0u;
}

__global__ void __launch_bounds__(TPB, 1)
k_fused(const float* __restrict__ s_in, const float* __restrict__ v_in,
        const float* __restrict__ p_in, const float* __restrict__ ea,
        const float* __restrict__ ln_g, const float* __restrict__ ln_b,
        const float* __restrict__ W1,  const float* __restrict__ b1,
        const float* __restrict__ W2,  const float* __restrict__ b2,
        const float* __restrict__ Wm1, const float* __restrict__ bm1,
        const float* __restrict__ Wm2, const float* __restrict__ bm2,
        const float* __restrict__ Wpre,const float* __restrict__ bpre,
        const float* __restrict__ Wpost,const float* __restrict__ bpost,
        float* __restrict__ out)
{
    extern __shared__ float sh[];
    int* shi = (int*)sh;
    const int tx   = threadIdx.x;
    const int grp  = tx >> 7;
    const int t128 = tx & 127;
    const int t    = tx & 63;
    const int lane = tx & 31;
    const int widx = tx >> 5;
    const bool lower = (t128 < 64);
    const int wrp  = t >> 5;
    const int gg   = blockIdx.x >> 4;
    const int cbase = gg << 6;
    const int i    = g_map[blockIdx.x*4 + grp];
    const int li   = i & 63;
    unsigned int epoch = 0;
    float* shHb = sh + SH_H + grp*140;

    float s_reg = s_in[i*SD + t];
    float v_reg = (t < 48) ? v_in[i*48 + t] : 0.0f;

    // -------- adjacency (lower 64 per node) --------
    if (lower) {
        float pix = p_in[i*3], piy = p_in[i*3+1], piz = p_in[i*3+2];
        int jg = cbase + t;
        float dx = p_in[jg*3]-pix, dy = p_in[jg*3+1]-piy, dz = p_in[jg*3+2]-piz;
        bool ok = (jg != i) && (dx*dx + dy*dy + dz*dz < 25.0f);
        unsigned m = __ballot_sync(0xffffffffu, ok);
        if (lane == 0) shi[SH_WCNT + grp*2 + wrp] = __popc(m);
        bar64(grp);
        int base = (wrp == 1) ? shi[SH_WCNT + grp*2] : 0;
        if (ok) shi[SH_NBR + grp*64 + base + __popc(m & ((1u << lane) - 1u))] = t;
        if (t == 0) {
            shi[SH_CNT + grp] = shi[SH_WCNT + grp*2] + shi[SH_WCNT + grp*2 + 1];
            shi[SH_LI + grp] = li;
        }
        bar64(grp);
    }
    __syncthreads();
    if (tx == 0) {
        int o = 0; shi[SH_OFF] = 0;
        #pragma unroll
        for (int n = 0; n < 4; n++) { o += shi[SH_CNT + n]; shi[SH_OFF + n + 1] = o; }
    }
    __syncthreads();
    const int cnt = shi[SH_CNT + grp];
    const float dinv = 1.0f / fmaxf((float)cnt, 1.0f);
    if (lower && t < cnt)
        shi[SH_IT + shi[SH_OFF + grp] + t] = (grp << 6) | shi[SH_NBR + grp*64 + t];
    __syncthreads();
    const int nit = shi[SH_OFF + 4];

    // E slice into smem
    for (int idx = tx; idx < nit*ED; idx += TPB) {
        int item = shi[SH_IT + (idx >> 4)];
        int c = idx & 15;
        int ig2 = item >> 6, j = item & 63;
        int lio = shi[SH_LI + ig2];
        int e = gg*EPG + lio*63 + j - (j > lio ? 1 : 0);
        sh[SH_EI + idx] = ea[(size_t)e*ED + c];
    }

    // -------- layers --------
    for (int l = 0; l < LL; l++) {
        const int pin = l & 1, pout = pin ^ 1;

        __syncthreads();
        {
            const float4* w1g = (const float4*)(W1 + (size_t)l*146*SD);
            float4* w1s = (float4*)(sh + SH_W1S);
            for (int idx = tx; idx < 128*SD/4; idx += TPB) w1s[idx] = w1g[idx];
        }
        __syncthreads();

        // ---- node_pre: LN + vnorm (lower 64), ci/cj dot (all 128) ----
        if (lower) {
            float xs = s_reg, xq = s_reg*s_reg;
            float xv = (t < 48) ? v_reg*v_reg : 0.0f;
            #pragma unroll
            for (int o = 16; o; o >>= 1) {
                xs += __shfl_down_sync(0xffffffffu, xs, o);
                xq += __shfl_down_sync(0xffffffffu, xq, o);
                xv += __shfl_down_sync(0xffffffffu, xv, o);
            }
            bar64(grp);
            if (lane == 0) {
                float* r = sh + SH_RED + grp*8 + wrp*3;
                r[0] = xs; r[1] = xq; r[2] = xv;
            }
            bar64(grp);
            const float* r = sh + SH_RED + grp*8;
            float mu   = (r[0] + r[3]) * (1.0f/64);
            float var  = (r[1] + r[4]) * (1.0f/64) - mu*mu;
            float vinv = rsqrtf((r[2] + r[5]) * (1.0f/16) + 1e-6f);
            s_reg = (s_reg - mu) * rsqrtf(fmaxf(var, 0.0f) + 1e-6f) * ln_g[l*SD + t] + ln_b[l*SD + t];
            shHb[t] = s_reg;
            if (t < 48) { v_reg *= vinv; g_vn[i*48 + t] = v_reg; }
            if (t < 3) {
                float p0 = g_p[pin][i*3], p1 = g_p[pin][i*3+1], p2 = g_p[pin][i*3+2];
                float inv = rsqrtf(p0*p0 + p1*p1 + p2*p2);
                g_pn[i*3 + t] = g_p[pin][i*3 + t] * inv;
            }
        }
        bar128(grp);
        {
            int which = t128 >> 6;
            const float* w1s = sh + SH_W1S + which*4096;
            float a0 = which ? 0.0f : b1[l*SD + t];
            float a1 = 0.0f;
            #pragma unroll 8
            for (int k = 0; k < SD; k += 2) {
                a0 += shHb[k]   * w1s[k*64 + t];
                a1 += shHb[k+1] * w1s[(k+1)*64 + t];
            }
            float acc = a0 + a1;
            if (which == 0) sh[SH_CI + grp*64 + t] = acc;
            else            g_cj[i*SD + t] = acc;
        }

        gsync(++epoch * NCTA);   // publishes cj/vn/pn/p(l) + f(l-1)

        // ---- stage group dynamics + weights ----
        {
            const float4* cjg = (const float4*)(g_cj + cbase*SD);
            float4* cjs = (float4*)(sh + SH_CJ);
            for (int idx = tx; idx < 64*SD/4; idx += TPB) cjs[idx] = cjg[idx];
            if (l > 0) {
                const float4* vg = (const float4*)(g_vn + cbase*48);
                float4* vs = (float4*)(sh + SH_V);
                for (int idx = tx; idx < 64*48/4; idx += TPB) vs[idx] = vg[idx];
                const float4* fg = (const float4*)(g_f + cbase*ED);
                float4* fs = (float4*)(sh + SH_F);
                for (int idx = tx; idx < 64*ED/4; idx += TPB) fs[idx] = fg[idx];
                for (int idx = tx; idx < ED*ED; idx += TPB)
                    sh[SH_WPS + idx] = Wpost[(l-1)*ED*ED + idx];
            }
            for (int idx = tx; idx < 192; idx += TPB) {
                sh[SH_P + idx]  = g_p[pin][cbase*3 + idx];
                sh[SH_PN + idx] = g_pn[cbase*3 + idx];
            }
            const float* w2g = W2 + (size_t)l*SD*DOUT;
            for (int idx = tx; idx < SD*DOUT; idx += TPB) {
                int kk = idx / DOUT, col = idx - kk*DOUT;
                float w = w2g[idx];
                if (col < 64) sh[SH_W2T + col*68 + kk] = w;
                else          sh[SH_W2T2 + (col-64)*68 + kk] = w;
            }
            // W1 tail rows 128..145, per-column transposed: T[col*20 + row]
            for (int idx = tx; idx < 64*18; idx += TPB) {
                int col = idx / 18, row = idx - col*18;
                sh[SH_W1TT + col*20 + row] = W1[(size_t)l*146*SD + (128+row)*SD + col];
            }
            for (int idx = tx; idx < 33; idx += TPB)
                sh[SH_TB + idx] = b2[l*DOUT + 64 + idx];
            if (l < LL-1) {
                const float4* m1 = (const float4*)(Wm1 + (size_t)l*SD*SD);
                const float4* m2 = (const float4*)(Wm2 + (size_t)l*SD*SD);
                float4* w1s = (float4*)(sh + SH_W1S);
                for (int idx = tx; idx < SD*SD/4; idx += TPB) {
                    w1s[idx] = m1[idx];
                    w1s[SD*SD/4 + idx] = m2[idx];
                }
            }
        }
        __syncthreads();

        // ---- edge update (layer l-1): 32 half-warp processors ----
        if (l > 0) {
            int hw = lane >> 4, e = lane & 15;
            float bp = bpost[(l-1)*ED + e];
            for (int b = widx*2; b < nit; b += 32) {
                int k = b + hw;
                bool act = (k < nit);
                int sl = act ? k : 0;
                int item = shi[SH_IT + sl];
                int ig2 = item >> 6, j = item & 63;
                float x = sh[SH_F + shi[SH_LI + ig2]*ED + e] + sh[SH_F + j*ED + e];
                float tv = sh[SH_EI + sl*ED + e] + silu(x);
                float o = bp;
                #pragma unroll
                for (int m = 0; m < ED; m++) {
                    float tm = __shfl_sync(0xffffffffu, tv, (hw << 4) + m);
                    o += tm * sh[SH_WPS + m*ED + e];
                }
                if (act) sh[SH_EI + sl*ED + e] = o;
            }
        }
        __syncthreads();

        // ---- pair phase: flat items across 16 warps ----
        {
            float* hb = sh + SH_HW + widx*64;
            const float b2g = sh[SH_TB + 32];
            const float4* Ta4 = (const float4*)(sh + SH_W1TT + lane*20);
            const float4* Tb4 = (const float4*)(sh + SH_W1TT + (lane+32)*20);
            const float*  Ta  = sh + SH_W1TT + lane*20;
            const float*  Tb  = sh + SH_W1TT + (lane+32)*20;
            const float4* wc4 = (const float4*)(sh + SH_W2T2 + lane*68);

            for (int k = widx; k < nit; k += 16) {
                int item = shi[SH_IT + k];
                int ig2 = item >> 6, j = item & 63;
                int lio = shi[SH_LI + ig2];

                float pix = sh[SH_P + lio*3], piy = sh[SH_P + lio*3+1], piz = sh[SH_P + lio*3+2];
                float dx = sh[SH_P + j*3]-pix, dy = sh[SH_P + j*3+1]-piy, dz = sh[SH_P + j*3+2]-piz;
                float dd = sqrtf(fmaxf(dx*dx + dy*dy + dz*dz, 1e-6f));
                float ac = sh[SH_PN + lio*3]*sh[SH_PN + j*3]
                         + sh[SH_PN + lio*3+1]*sh[SH_PN + j*3+1]
                         + sh[SH_PN + lio*3+2]*sh[SH_PN + j*3+2];
                float env = 0.5f*(__cosf(dd*0.62831853f) + 1.0f);
                float ri = 1.0f/(1.0f + dd);
                float rnx = dx*ri, rny = dy*ri, rnz = dz*ri;

                const float4* Ep = (const float4*)(sh + SH_EI + k*ED);
                float4 E0 = Ep[0], E1 = Ep[1], E2 = Ep[2], E3 = Ep[3];

                float hvA = sh[SH_CI + ig2*64 + lane]      + sh[SH_CJ + j*SD + lane];
                float hvB = sh[SH_CI + ig2*64 + 32 + lane] + sh[SH_CJ + j*SD + 32 + lane];
                {
                    float4 w0 = Ta4[0], w1 = Ta4[1], w2 = Ta4[2], w3 = Ta4[3];
                    hvA += dd*w0.x + ac*w0.y + E0.x*w0.z + E0.y*w0.w
                         + E0.z*w1.x + E0.w*w1.y + E1.x*w1.z + E1.y*w1.w
                         + E1.z*w2.x + E1.w*w2.y + E2.x*w2.z + E2.y*w2.w
                         + E2.z*w3.x + E2.w*w3.y + E3.x*w3.z + E3.y*w3.w
                         + E3.z*Ta[16] + E3.w*Ta[17];
                }
                {
                    float4 w0 = Tb4[0], w1 = Tb4[1], w2 = Tb4[2], w3 = Tb4[3];
                    hvB += dd*w0.x + ac*w0.y + E0.x*w0.z + E0.y*w0.w
                         + E0.z*w1.x + E0.w*w1.y + E1.x*w1.z + E1.y*w1.w
                         + E1.z*w2.x + E1.w*w2.y + E2.x*w2.z + E2.y*w2.w
                         + E2.z*w3.x + E2.w*w3.y + E3.x*w3.z + E3.y*w3.w
                         + E3.z*Tb[16] + E3.w*Tb[17];
                }
                float hpA = silu(hvA)*env;
                float hpB = silu(hvB)*env;

                float gcp = hpA*sh[SH_W2T2 + 32*68 + lane] + hpB*sh[SH_W2T2 + 32*68 + 32 + lane];
                #pragma unroll
                for (int o = 16; o; o >>= 1) gcp += __shfl_xor_sync(0xffffffffu, gcp, o);
                float gc = gcp + b2g*env;

                hb[lane] = hpA; hb[32 + lane] = hpB;
                __syncwarp();
                const float4* h4 = (const float4*)hb;
                float a0=0,a1=0,a2=0,a3=0;
                #pragma unroll
                for (int q = 0; q < 16; q++) {
                    float4 h = h4[q];
                    float4 w = wc4[q];
                    a0 += h.x*w.x; a1 += h.y*w.y;
                    a2 += h.z*w.z; a3 += h.w*w.w;
                }
                float tailv = (a0+a1)+(a2+a3) + sh[SH_TB + lane]*env;
                __syncwarp();

                int d = lane & 15;
                float gr = __shfl_sync(0xffffffffu, tailv, d);
                float gv = __shfl_sync(0xffffffffu, tailv, 16 + d);
                float rnA = (lane < 16) ? rnx : rny;
                float vA = rnA*gr;
                float vB = rnz*gr;
                if (l > 0) {
                    vA += sh[SH_V + j*48 + lane]*gv;
                    if (lane < 16) vB += sh[SH_V + j*48 + 32 + lane]*gv;
                }
                float* rec = sh + SH_REC + k*RS;
                rec[lane]      = hpA;
                rec[32 + lane] = hpB;
                rec[64 + lane] = vA;
                if (lane < 16) rec[96 + lane] = vB;
                if (lane < 3)  rec[112 + lane] = gc * ((lane==0)?rnx:((lane==1)?rny:rnz));
                if (lane == 0) rec[115] = env;
            }
        }
        __syncthreads();
        for (int idx = tx; idx < SD*ED; idx += TPB)
            sh[SH_W1TT + idx] = Wpre[(size_t)l*SD*ED + idx];
        __syncthreads();

        // ---- owner reduction + state update + node_post (lower 64) ----
        if (lower) {
            int o0 = shi[SH_OFF + grp], o1 = shi[SH_OFF + grp + 1];
            float h0 = 0.0f, h1 = 0.0f, b0v = 0.0f, b1v = 0.0f;
            int k = o0;
            for (; k + 1 < o1; k += 2) {
                h0 += sh[SH_REC + k*RS + t];
                h1 += sh[SH_REC + (k+1)*RS + t];
                if (t < 52) {
                    b0v += sh[SH_REC + k*RS + 64 + t];
                    b1v += sh[SH_REC + (k+1)*RS + 64 + t];
                }
            }
            if (k < o1) {
                h0 += sh[SH_REC + k*RS + t];
                if (t < 52) b0v += sh[SH_REC + k*RS + 64 + t];
            }
            float henv = h0 + h1, accb = b0v + b1v;
            shHb[t] = henv;
            if (t == 51) sh[SH_ENV + grp] = accb;
            bar64(grp);
            float envs = sh[SH_ENV + grp];
            {
                const float4* hs = (const float4*)shHb;
                const float4* wc = (const float4*)(sh + SH_W2T + t*68);
                float a0=0,a1=0,a2=0,a3=0;
                #pragma unroll
                for (int q = 0; q < 16; q++) {
                    float4 h4 = hs[q];
                    float4 w4 = wc[q];
                    a0 += h4.x*w4.x; a1 += h4.y*w4.y;
                    a2 += h4.z*w4.z; a3 += h4.w*w4.w;
                }
                s_reg += (a0+a1)+(a2+a3) + b2[l*DOUT + t]*envs;
            }
            if (t < 48) v_reg += accb * dinv;
            if (t >= 48 && t < 51)
                g_p[pout][i*3 + (t-48)] = sh[SH_P + li*3 + (t-48)] + accb * dinv;
            bar64(grp);

            if (l < LL-1) {
                shHb[t] = s_reg;
                bar64(grp);
                const float* wm1 = sh + SH_W1S;
                float m0 = bm1[l*SD + t], m1 = 0.0f;
                #pragma unroll 8
                for (int kk = 0; kk < SD; kk += 2) {
                    m0 += shHb[kk]   * wm1[kk*SD + t];
                    m1 += shHb[kk+1] * wm1[(kk+1)*SD + t];
                }
                float hm = silu(m0 + m1);
                shHb[68 + t] = hm;
                bar64(grp);
                const float* wm2 = sh + SH_W1S + SD*SD;
                float q0 = bm2[l*SD + t], q1 = 0.0f;
                #pragma unroll 8
                for (int kk = 0; kk < SD; kk += 2) {
                    q0 += shHb[68+kk]   * wm2[kk*SD + t];
                    q1 += shHb[68+kk+1] * wm2[(kk+1)*SD + t];
                }
                s_reg += q0 + q1;
                bar64(grp);
            }
            shHb[t] = s_reg;
            bar64(grp);
            if (t < ED) {
                const float* wp = sh + SH_W1TT;
                float f0 = bpre[l*ED + t], f1 = 0.0f;
                #pragma unroll 8
                for (int kk = 0; kk < SD; kk += 2) {
                    f0 += shHb[kk]   * wp[kk*ED + t];
                    f1 += shHb[kk+1] * wp[(kk+1)*ED + t];
                }
                g_f[i*ED + t] = f0 + f1;
            }
        }
    }

    gsync(++epoch * NCTA);   // publish f(LL-1)

    // ---- final edge update ----
    {
        const float4* fg = (const float4*)(g_f + cbase*ED);
        float4* fs = (float4*)(sh + SH_F);
        for (int idx = tx; idx < 64*ED/4; idx += TPB) fs[idx] = fg[idx];
        for (int idx = tx; idx < ED*ED; idx += TPB)
            sh[SH_WPS + idx] = Wpost[(LL-1)*ED*ED + idx];
    }
    __syncthreads();
    {
        int hw = lane >> 4, e = lane & 15;
        float bp = bpost[(LL-1)*ED + e];
        for (int b = widx*2; b < nit; b += 32) {
            int k = b + hw;
            bool act = (k < nit);
            int sl = act ? k : 0;
            int item = shi[SH_IT + sl];
            int ig2 = item >> 6, j = item & 63;
            float x = sh[SH_F + shi[SH_LI + ig2]*ED + e] + sh[SH_F + j*ED + e];
            float tv = sh[SH_EI + sl*ED + e] + silu(x);
            float o = bp;
            #pragma unroll
            for (int m = 0; m < ED; m++) {
                float tm = __shfl_sync(0xffffffffu, tv, (hw << 4) + m);
                o += tm * sh[SH_WPS + m*ED + e];
            }
            if (act) sh[SH_EI + sl*ED + e] = o;
        }
    }
    __syncthreads();

    // -------- output --------
    if (lower) {
        out[i*SD + t] = s_reg;
        if (t < 48) out[OFF_V + i*48 + t] = v_reg;
        if (t < 3)  out[OFF_P + i*3 + t] = g_p[LL & 1][i*3 + t];
    }
    for (int idx = tx; idx < nit*ED; idx += TPB) {
        int item = shi[SH_IT + (idx >> 4)];
        int c = idx & 15;
        int ig2 = item >> 6, j = item & 63;
        int lio = shi[SH_LI + ig2];
        int e = gg*EPG + lio*63 + j - (j > lio ? 1 : 0);
        out[OFF_E + (size_t)e*ED + c] = sh[SH_EI + idx];
    }
    {
        const int e0 = blockIdx.x * (8*EPG / NCTA);
        for (int q = tx; q < (8*EPG/NCTA)*ED; q += TPB) {
            int e = e0 + (q >> 4), c = q & 15;
            int gg2 = e / EPG, rem = e - gg2*EPG;
            int si = rem / 63, t63 = rem - si*63;
            int ti = t63 + (t63 >= si ? 1 : 0);
            int a = gg2*64 + si, b = gg2*64 + ti;
            float dx = p_in[a*3]   - p_in[b*3];
            float dy = p_in[a*3+1] - p_in[b*3+1];
            float dz = p_in[a*3+2] - p_in[b*3+2];
            if (!(dx*dx + dy*dy + dz*dz < 25.0f))
                out[OFF_E + (size_t)e*ED + c] = ea[(size_t)e*ED + c];
        }
    }
}

// ---------------- launch ----------------
extern "C" void kernel_launch(void* const* d_in, const int* in_sizes, int n_in,
                              void* d_out, int out_size) {
    const float* s    = (const float*)d_in[0];
    const float* v    = (const float*)d_in[1];
    const float* p    = (const float*)d_in[2];
    const float* ea   = (const float*)d_in[3];
    const float* ln_g = (const float*)d_in[6];
    const float* ln_b = (const float*)d_in[7];
    const float* W1   = (const float*)d_in[8];
    const float* b1   = (const float*)d_in[9];
    const float* W2   = (const float*)d_in[10];
    const float* b2   = (const float*)d_in[11];
    const float* Wm1  = (const float*)d_in[12];
    const float* bm1  = (const float*)d_in[13];
    const float* Wm2  = (const float*)d_in[14];
    const float* bm2  = (const float*)d_in[15];
    const float* Wpre = (const float*)d_in[16];
    const float* bpre = (const float*)d_in[17];
    const float* Wpost= (const float*)d_in[18];
    const float* bpost= (const float*)d_in[19];
    float* out = (float*)d_out;

    cudaFuncSetAttribute(k_fused, cudaFuncAttributeMaxDynamicSharedMemorySize, SMEM_BYTES);
    k_init<<<1, NN>>>(p);
    k_fused<<<NCTA, TPB, SMEM_BYTES>>>(s, v, p, ea, ln_g, ln_b, W1, b1, W2, b2,
                                       Wm1, bm1, Wm2, bm2, Wpre, bpre, Wpost, bpost, out);
}